// round 6
// baseline (speedup 1.0000x reference)
#include <cuda_runtime.h>
#include <cuda_bf16.h>
#include <cstdint>

// Problem shapes (fixed by the dataset's setup_inputs)
constexpr int B = 16;
constexpr int S = 512;
constexpr int D = 768;     // span_dim
constexpr int E = 128;     // distance embedding dim
constexpr int T = 64;
constexpr int O = 64;
constexpr int P = T * O;            // 4096 pairs per batch
constexpr int OUT_D = 2 * D + E;    // 1664 floats per output row
constexpr int D4 = D / 4;           // 192 float4
constexpr int E4 = E / 4;           // 32 float4
constexpr int OUT_D4 = OUT_D / 4;   // 416 float4
constexpr int NBINS = 14;

// bucket = (# bins <= width) - 1; bins[0]=0 and width>=0,
// so bucket = sum_{i=1..13} (width >= bins[i]).
__constant__ int c_bins[NBINS] = {0, 1, 2, 3, 4, 5, 7, 8, 15, 16, 31, 32, 63, 64};

__device__ __forceinline__ int bucketize(int w) {
    int bucket = 0;
#pragma unroll
    for (int i = 1; i < NBINS; ++i)
        bucket += (w >= c_bins[i]) ? 1 : 0;
    return bucket;
}

// One block handles a 2x2 tile: targets (2tg, 2tg+1) x opinions (2og, 2og+1).
// 4 output rows from only 4 span loads per thread. Dist phase deferred so its
// registers reuse the span registers (keeps regs <= 34 for 10 blocks/SM).
__global__ __launch_bounds__(192, 10)
void pair_rep_kernel(const float4* __restrict__ spans,      // [B,S,D/4]
                     const float4* __restrict__ dist_emb,   // [14,E/4]
                     const int2*   __restrict__ span_idx,   // [S]
                     const int*    __restrict__ tgt,        // [B,T]
                     const int*    __restrict__ opi,        // [B,O]
                     float4*       __restrict__ out)        // [B*P, OUT_D/4]
{
    const int blk = blockIdx.x;            // 0 .. B*(T/2)*(O/2)-1 = 16383
    const int b   = blk >> 10;             // / 1024
    const int r   = blk & 1023;
    const int tg  = r >> 5;                // target group 0..31
    const int og  = r & 31;                // opinion group 0..31
    const int t0  = 2 * tg;
    const int o0  = 2 * og;

    const int ti0 = __ldg(&tgt[b * T + t0]);
    const int ti1 = __ldg(&tgt[b * T + t0 + 1]);
    const int oiA = __ldg(&opi[b * O + o0]);
    const int oiB = __ldg(&opi[b * O + o0 + 1]);

    const int tid = threadIdx.x;           // 0..191 == D4
    const float4* spb = spans + (size_t)b * S * D4;

    // Span loads first — 4 independent loads in flight
    const float4 vt0 = __ldg(&spb[(size_t)ti0 * D4 + tid]);
    const float4 vt1 = __ldg(&spb[(size_t)ti1 * D4 + tid]);
    const float4 voA = __ldg(&spb[(size_t)oiA * D4 + tid]);
    const float4 voB = __ldg(&spb[(size_t)oiB * D4 + tid]);

    // Row bases: rows (t0,o0),(t0,o0+1) adjacent; t1 rows are O rows later
    float4* dst0 = out + ((size_t)b * P + (size_t)t0 * O + o0) * OUT_D4;
    float4* dst1 = dst0 + (size_t)O * OUT_D4;

    // Span sections (8 streaming stores)
    __stcs(&dst0[tid], vt0);
    __stcs(&dst0[D4 + tid], voA);
    __stcs(&dst0[OUT_D4 + tid], vt0);
    __stcs(&dst0[OUT_D4 + D4 + tid], voB);
    __stcs(&dst1[tid], vt1);
    __stcs(&dst1[D4 + tid], voA);
    __stcs(&dst1[OUT_D4 + tid], vt1);
    __stcs(&dst1[OUT_D4 + D4 + tid], voB);

    // Dist phase — deferred so these registers reuse the (now dead) span regs.
    // dist_emb is 7 KB -> permanently cache-resident; latency hidden by warps.
    if (tid < E4) {
        const int2 ab0 = __ldg(&span_idx[ti0]);
        const int2 ab1 = __ldg(&span_idx[ti1]);
        const int2 cdA = __ldg(&span_idx[oiA]);
        const int2 cdB = __ldg(&span_idx[oiB]);

        const int bk0A = bucketize(min(abs(ab0.y - cdA.x), abs(ab0.x - cdA.y)));
        const int bk0B = bucketize(min(abs(ab0.y - cdB.x), abs(ab0.x - cdB.y)));
        const int bk1A = bucketize(min(abs(ab1.y - cdA.x), abs(ab1.x - cdA.y)));
        const int bk1B = bucketize(min(abs(ab1.y - cdB.x), abs(ab1.x - cdB.y)));

        const float4 vd0A = __ldg(&dist_emb[(size_t)bk0A * E4 + tid]);
        const float4 vd0B = __ldg(&dist_emb[(size_t)bk0B * E4 + tid]);
        const float4 vd1A = __ldg(&dist_emb[(size_t)bk1A * E4 + tid]);
        const float4 vd1B = __ldg(&dist_emb[(size_t)bk1B * E4 + tid]);

        __stcs(&dst0[2 * D4 + tid], vd0A);
        __stcs(&dst0[OUT_D4 + 2 * D4 + tid], vd0B);
        __stcs(&dst1[2 * D4 + tid], vd1A);
        __stcs(&dst1[OUT_D4 + 2 * D4 + tid], vd1B);
    }
}

extern "C" void kernel_launch(void* const* d_in, const int* in_sizes, int n_in,
                              void* d_out, int out_size)
{
    // metadata order: spans, dist_emb, span_indices, target_indices, opinion_indices
    const float4* spans    = (const float4*)d_in[0];
    const float4* dist_emb = (const float4*)d_in[1];
    const int2*   span_idx = (const int2*)  d_in[2];
    const int*    tgt      = (const int*)   d_in[3];
    const int*    opi      = (const int*)   d_in[4];
    float4*       out      = (float4*)d_out;

    dim3 grid(B * (T / 2) * (O / 2));   // 16384 blocks, 2x2 tile each
    dim3 block(192);
    pair_rep_kernel<<<grid, block>>>(spans, dist_emb, span_idx, tgt, opi, out);
}

// round 7
// speedup vs baseline: 1.0149x; 1.0149x over previous
#include <cuda_runtime.h>
#include <cuda_bf16.h>
#include <cstdint>

// Problem shapes (fixed by the dataset's setup_inputs)
constexpr int B = 16;
constexpr int S = 512;
constexpr int D = 768;     // span_dim
constexpr int E = 128;     // distance embedding dim
constexpr int T = 64;
constexpr int O = 64;
constexpr int P = T * O;            // 4096 pairs per batch
constexpr int OUT_D = 2 * D + E;    // 1664 floats per output row
constexpr int D4 = D / 4;           // 192 float4
constexpr int E4 = E / 4;           // 32 float4
constexpr int OUT_D4 = OUT_D / 4;   // 416 float4
constexpr int NBINS = 14;

// bucket = (# bins <= width) - 1; bins[0]=0 and width>=0,
// so bucket = sum_{i=1..13} (width >= bins[i]).
__constant__ int c_bins[NBINS] = {0, 1, 2, 3, 4, 5, 7, 8, 15, 16, 31, 32, 63, 64};

__device__ __forceinline__ int bucketize(int w) {
    int bucket = 0;
#pragma unroll
    for (int i = 1; i < NBINS; ++i)
        bucket += (w >= c_bins[i]) ? 1 : 0;
    return bucket;
}

// One block = 224 threads (7 warps) handles 2 output rows (same target,
// adjacent opinions). Warps 0-5 (tid 0..191) do span copy; warp 6
// (tid 192..223) does the distance-embedding sections. No intra-warp
// divergence; dist work overlaps span work instead of trailing it.
__global__ __launch_bounds__(224, 9)
void pair_rep_kernel(const float4* __restrict__ spans,      // [B,S,D/4]
                     const float4* __restrict__ dist_emb,   // [14,E/4]
                     const int2*   __restrict__ span_idx,   // [S]
                     const int*    __restrict__ tgt,        // [B,T]
                     const int*    __restrict__ opi,        // [B,O]
                     float4*       __restrict__ out)        // [B*P, OUT_D/4]
{
    const int blk = blockIdx.x;            // 0 .. B*T*(O/2)-1 = 32767
    const int b   = blk >> 11;             // / 2048
    const int r   = blk & 2047;
    const int t   = r >> 5;                // / 32
    const int g   = r & 31;                // opinion pair group
    const int o0  = 2 * g;

    const int ti  = __ldg(&tgt[b * T + t]);
    const int oiA = __ldg(&opi[b * O + o0]);
    const int oiB = __ldg(&opi[b * O + o0 + 1]);

    const int tid = threadIdx.x;

    float4* dst0 = out + ((size_t)b * P + (size_t)t * O + o0) * OUT_D4;
    float4* dst1 = dst0 + OUT_D4;

    if (tid < D4) {
        // ---- span warps (0-5): 3 loads, 4 streaming stores ----
        const float4* spb = spans + (size_t)b * S * D4;
        const float4 vt  = __ldg(&spb[(size_t)ti  * D4 + tid]);
        const float4 voA = __ldg(&spb[(size_t)oiA * D4 + tid]);
        const float4 voB = __ldg(&spb[(size_t)oiB * D4 + tid]);

        __stcs(&dst0[tid], vt);
        __stcs(&dst0[D4 + tid], voA);
        __stcs(&dst1[tid], vt);
        __stcs(&dst1[D4 + tid], voB);
    } else {
        // ---- dist warp (6): buckets + embedding sections for both rows ----
        const int d = tid - D4;            // 0..31 == E4 lanes

        const int2 ab = __ldg(&span_idx[ti]);
        const int2 cdA = __ldg(&span_idx[oiA]);
        const int2 cdB = __ldg(&span_idx[oiB]);
        const int bkA = bucketize(min(abs(ab.y - cdA.x), abs(ab.x - cdA.y)));
        const int bkB = bucketize(min(abs(ab.y - cdB.x), abs(ab.x - cdB.y)));

        const float4 vdA = __ldg(&dist_emb[(size_t)bkA * E4 + d]);
        const float4 vdB = __ldg(&dist_emb[(size_t)bkB * E4 + d]);

        __stcs(&dst0[2 * D4 + d], vdA);
        __stcs(&dst1[2 * D4 + d], vdB);
    }
}

extern "C" void kernel_launch(void* const* d_in, const int* in_sizes, int n_in,
                              void* d_out, int out_size)
{
    // metadata order: spans, dist_emb, span_indices, target_indices, opinion_indices
    const float4* spans    = (const float4*)d_in[0];
    const float4* dist_emb = (const float4*)d_in[1];
    const int2*   span_idx = (const int2*)  d_in[2];
    const int*    tgt      = (const int*)   d_in[3];
    const int*    opi      = (const int*)   d_in[4];
    float4*       out      = (float4*)d_out;

    dim3 grid(B * T * (O / 2));   // 32768 blocks, two rows each
    dim3 block(224);              // 6 span warps + 1 dist warp
    pair_rep_kernel<<<grid, block>>>(spans, dist_emb, span_idx, tgt, opi, out);
}